// round 15
// baseline (speedup 1.0000x reference)
#include <cuda_runtime.h>
#include <cstdint>

#define NN     100000
#define NFEAT  512
#define HID    16
#define NCLASS 40
#define EMAX   3200000

// ---------------- scratch (static device globals; no allocation) ----------------
__device__ float g_deg[NN];
__device__ float g_dinv[NN];
__device__ float g_W1[NFEAT * 64];          // packed [f][c]: c<32 -> iw1[k=c/16][f][c%16], c>=32 -> rw1
__device__ float g_HR[(size_t)NN * 64];     // [n][c]: c<32 = x@iw1 (k-major), c>=32 = x@rw1
__device__ float g_agg1[(size_t)NN * 32];   // scatter target layer 1
__device__ float g_h1[NN * HID];            // layer-1 output
__device__ float g_agg2[NN * HID];          // scatter target layer 2 (pre-transform)
__device__ float g_W2[HID * 160];           // packed [f][c]: c<80 -> iw2[k][f][c%40], c>=80 -> rw2

// ---------------- helpers ----------------
__device__ __forceinline__ void red_add_v4(float* p, float a, float b, float c, float d) {
    asm volatile("red.global.add.v4.f32 [%0], {%1,%2,%3,%4};"
                 :: "l"(p), "f"(a), "f"(b), "f"(c), "f"(d) : "memory");
}

// ---------------- setup kernels ----------------
__global__ void zero_kernel() {
    int i = blockIdx.x * blockDim.x + threadIdx.x;
    if (i < NN) g_deg[i] = 0.f;
    if (i < NN * 32) g_agg1[i] = 0.f;
    if (i < NN * 16) g_agg2[i] = 0.f;
}

__global__ void pack_w1(const float* __restrict__ iw1, const float* __restrict__ rw1) {
    int i = blockIdx.x * blockDim.x + threadIdx.x;
    if (i >= NFEAT * 64) return;
    int f = i >> 6, c = i & 63;
    float v;
    if (c < 32) { int k = c >> 4, j = c & 15; v = iw1[(k * NFEAT + f) * HID + j]; }
    else        { int c2 = c - 32; int k = c2 >> 4, j = c2 & 15; v = rw1[(k * NFEAT + f) * HID + j]; }
    g_W1[i] = v;
}

__global__ void pack_w2(const float* __restrict__ iw2, const float* __restrict__ rw2) {
    int i = blockIdx.x * blockDim.x + threadIdx.x;
    if (i >= HID * 160) return;
    int f = i / 160, c = i % 160;
    float v;
    if (c < 80) { int k = c / 40, o = c % 40; v = iw2[(k * HID + f) * NCLASS + o]; }
    else        { int c2 = c - 80; int k = c2 / 40, o = c2 % 40; v = rw2[(k * HID + f) * NCLASS + o]; }
    g_W2[i] = v;
}

__global__ void deg_kernel(const int* __restrict__ dst, int E) {
    int e = blockIdx.x * blockDim.x + threadIdx.x;
    if (e < E) atomicAdd(&g_deg[__ldg(dst + e)], 1.0f);
}

__global__ void dinv_kernel() {
    int n = blockIdx.x * blockDim.x + threadIdx.x;
    if (n < NN) { float d = g_deg[n]; g_dinv[n] = (d > 0.f) ? rsqrtf(d) : 0.f; }
}

// ---------------- dense: HR[100000,64] = x[100000,512] @ W1[512,64] --------------
// 256 threads, block tile 256x64, thread tile 8x8, double-buffered smem.
#define GM 256
#define GK 16
#define NT (NFEAT / GK)   // 32 k-tiles
__global__ void __launch_bounds__(256, 2) gemm1_kernel(const float* __restrict__ x, int nrows) {
    __shared__ float As[2][GK][GM + 8];      // [buf][k][m]
    __shared__ float Bs[2][GK][64];          // [buf][k][n]
    int tid = threadIdx.x;                   // 256 threads
    int tx = tid & 7, ty = tid >> 3;         // 8 col-groups x 32 row-groups
    int brow = blockIdx.x * GM;

    int ar  = tid >> 2;                      // A base row (+64 per it)
    int ac4 = tid & 3;                       // A float4 index within k-tile
    int br  = tid >> 4;                      // B k-row
    int bc4 = tid & 15;                      // B float4 col

    float acc[8][8];
#pragma unroll
    for (int i = 0; i < 8; i++)
#pragma unroll
        for (int j = 0; j < 8; j++) acc[i][j] = 0.f;

    float4 pa[4];
    float4 pb;

    // prologue: load tile 0
#pragma unroll
    for (int it = 0; it < 4; ++it) {
        int gr = brow + ar + it * 64;
        pa[it] = (gr < nrows) ? *(const float4*)&x[(size_t)gr * NFEAT + ac4 * 4]
                              : make_float4(0.f, 0.f, 0.f, 0.f);
    }
    pb = *(const float4*)&g_W1[br * 64 + bc4 * 4];
#pragma unroll
    for (int it = 0; it < 4; ++it) {
        int r = ar + it * 64;
        As[0][ac4 * 4 + 0][r] = pa[it].x;
        As[0][ac4 * 4 + 1][r] = pa[it].y;
        As[0][ac4 * 4 + 2][r] = pa[it].z;
        As[0][ac4 * 4 + 3][r] = pa[it].w;
    }
    *(float4*)&Bs[0][br][bc4 * 4] = pb;
    __syncthreads();

    for (int t = 0; t < NT; ++t) {
        int cur = t & 1;
        if (t < NT - 1) {
            int k0 = (t + 1) * GK;
#pragma unroll
            for (int it = 0; it < 4; ++it) {
                int gr = brow + ar + it * 64;
                pa[it] = (gr < nrows)
                    ? *(const float4*)&x[(size_t)gr * NFEAT + k0 + ac4 * 4]
                    : make_float4(0.f, 0.f, 0.f, 0.f);
            }
            pb = *(const float4*)&g_W1[(k0 + br) * 64 + bc4 * 4];
        }
#pragma unroll
        for (int kk = 0; kk < GK; ++kk) {
            float a[8], b[8];
            *(float4*)&a[0] = *(const float4*)&As[cur][kk][ty * 8];
            *(float4*)&a[4] = *(const float4*)&As[cur][kk][ty * 8 + 4];
            *(float4*)&b[0] = *(const float4*)&Bs[cur][kk][tx * 8];
            *(float4*)&b[4] = *(const float4*)&Bs[cur][kk][tx * 8 + 4];
#pragma unroll
            for (int i = 0; i < 8; i++)
#pragma unroll
                for (int j = 0; j < 8; j++) acc[i][j] += a[i] * b[j];
        }
        if (t < NT - 1) {
            int nxt = (t + 1) & 1;
#pragma unroll
            for (int it = 0; it < 4; ++it) {
                int r = ar + it * 64;
                As[nxt][ac4 * 4 + 0][r] = pa[it].x;
                As[nxt][ac4 * 4 + 1][r] = pa[it].y;
                As[nxt][ac4 * 4 + 2][r] = pa[it].z;
                As[nxt][ac4 * 4 + 3][r] = pa[it].w;
            }
            *(float4*)&Bs[nxt][br][bc4 * 4] = pb;
            __syncthreads();
        }
    }
#pragma unroll
    for (int i = 0; i < 8; i++) {
        int gr = brow + ty * 8 + i;
        if (gr < nrows) {
            *(float4*)&g_HR[(size_t)gr * 64 + tx * 8] =
                make_float4(acc[i][0], acc[i][1], acc[i][2], acc[i][3]);
            *(float4*)&g_HR[(size_t)gr * 64 + tx * 8 + 4] =
                make_float4(acc[i][4], acc[i][5], acc[i][6], acc[i][7]);
        }
    }
}

// ---------------- layer-1 scatter: agg1[dst] += w * HR[src, 0:32] -----------------
// w computed inline (ew kernel fused away). 4 threads/edge, 8 floats each.
__global__ void edge1_kernel(const int* __restrict__ src, const int* __restrict__ dst, int E) {
    int idx = blockIdx.x * blockDim.x + threadIdx.x;
    if (idx >= E * 4) return;
    int e = idx >> 2, g = idx & 3;
    int s = __ldg(src + e), d = __ldg(dst + e);
    float w = __ldg(&g_dinv[s]) * __ldg(&g_dinv[d]);
    const float* hp = &g_HR[(size_t)s * 64 + g * 8];
    float4 v0 = *(const float4*)(hp);
    float4 v1 = *(const float4*)(hp + 4);
    float* ap = &g_agg1[(size_t)d * 32 + g * 8];
    red_add_v4(ap,     v0.x * w, v0.y * w, v0.z * w, v0.w * w);
    red_add_v4(ap + 4, v1.x * w, v1.y * w, v1.z * w, v1.w * w);
}

// ---------------- layer-1 epilogue: h1 = mean_k relu(agg1 + x@rw1 + b1) -----------
__global__ void epi1_kernel(const float* __restrict__ b1, int nrows) {
    int i = blockIdx.x * blockDim.x + threadIdx.x;
    if (i >= nrows * HID) return;
    int n = i / HID, j = i - (i / HID) * HID;
    float a0 = g_agg1[(size_t)n * 32 + j]      + g_HR[(size_t)n * 64 + 32 + j] + b1[j];
    float a1 = g_agg1[(size_t)n * 32 + 16 + j] + g_HR[(size_t)n * 64 + 48 + j] + b1[16 + j];
    g_h1[i] = 0.5f * (fmaxf(a0, 0.f) + fmaxf(a1, 0.f));
}

// ---------------- layer-2 scatter (pre-transform): agg2[dst] += w * h1[src] -------
// 2 threads/edge, 8 floats each.
__global__ void edge2_kernel(const int* __restrict__ src, const int* __restrict__ dst, int E) {
    int idx = blockIdx.x * blockDim.x + threadIdx.x;
    if (idx >= E * 2) return;
    int e = idx >> 1, g = idx & 1;
    int s = __ldg(src + e), d = __ldg(dst + e);
    float w = __ldg(&g_dinv[s]) * __ldg(&g_dinv[d]);
    const float* hp = &g_h1[s * HID + g * 8];
    float4 v0 = *(const float4*)(hp);
    float4 v1 = *(const float4*)(hp + 4);
    float* ap = &g_agg2[d * HID + g * 8];
    red_add_v4(ap,     v0.x * w, v0.y * w, v0.z * w, v0.w * w);
    red_add_v4(ap + 4, v1.x * w, v1.y * w, v1.z * w, v1.w * w);
}

// ---------------- layer-2 transform + epilogue ------------------------------------
__global__ void out_kernel(const float* __restrict__ b2, float* __restrict__ out, int nrows) {
    __shared__ float Ws[HID * 160];
    int tid = threadIdx.x;                   // 320 threads: 8 nodes x 40 outputs
    for (int i = tid; i < HID * 160; i += 320) Ws[i] = g_W2[i];
    __syncthreads();
    int n = blockIdx.x * 8 + tid / 40;
    int o = tid - (tid / 40) * 40;
    if (n >= nrows) return;
    float a[HID], hv[HID];
#pragma unroll
    for (int f = 0; f < HID; ++f) {
        a[f]  = g_agg2[n * HID + f];
        hv[f] = g_h1[n * HID + f];
    }
    float acc0 = b2[o], acc1 = b2[40 + o];
#pragma unroll
    for (int f = 0; f < HID; ++f) {
        const float* wr = &Ws[f * 160];
        acc0 += a[f] * wr[o]      + hv[f] * wr[80 + o];
        acc1 += a[f] * wr[40 + o] + hv[f] * wr[120 + o];
    }
    out[n * 40 + o] = 0.5f * (fmaxf(acc0, 0.f) + fmaxf(acc1, 0.f));
}

// ---------------- launch ----------------
extern "C" void kernel_launch(void* const* d_in, const int* in_sizes, int n_in,
                              void* d_out, int out_size) {
    const float* x   = (const float*)d_in[0];
    const int*   ei  = (const int*)d_in[1];
    const float* iw1 = (const float*)d_in[2];
    const float* rw1 = (const float*)d_in[3];
    const float* b1  = (const float*)d_in[4];
    const float* iw2 = (const float*)d_in[5];
    const float* rw2 = (const float*)d_in[6];
    const float* b2  = (const float*)d_in[7];
    float* out = (float*)d_out;

    int E = in_sizes[1] / 2;
    const int* src = ei;
    const int* dst = ei + E;

    // gemm1 kept in launch slot 4 (the slot ncu profiles).
    zero_kernel<<<(NN * 32 + 255) / 256, 256>>>();
    pack_w1<<<(NFEAT * 64 + 255) / 256, 256>>>(iw1, rw1);
    pack_w2<<<(HID * 160 + 255) / 256, 256>>>(iw2, rw2);
    gemm1_kernel<<<(NN + GM - 1) / GM, 256>>>(x, NN);
    deg_kernel<<<(E + 255) / 256, 256>>>(dst, E);
    dinv_kernel<<<(NN + 255) / 256, 256>>>();
    edge1_kernel<<<(E * 4 + 255) / 256, 256>>>(src, dst, E);
    epi1_kernel<<<(NN * HID + 255) / 256, 256>>>(b1, NN);
    edge2_kernel<<<(E * 2 + 255) / 256, 256>>>(src, dst, E);
    out_kernel<<<(NN + 7) / 8, 320>>>(b2, out, NN);
}

// round 16
// speedup vs baseline: 1.0903x; 1.0903x over previous
#include <cuda_runtime.h>
#include <cstdint>

#define NN     100000
#define NFEAT  512
#define HID    16
#define NCLASS 40
#define EMAX   3200000

// ---------------- scratch (static device globals; no allocation) ----------------
__device__ float g_deg[NN];
__device__ float g_dinv[NN];
__device__ float g_ew[EMAX];
__device__ float g_W1[NFEAT * 64];          // packed [f][c]: c<32 -> iw1[k=c/16][f][c%16], c>=32 -> rw1
__device__ float g_HR[(size_t)NN * 64];     // [n][c]: c<32 = x@iw1 (k-major), c>=32 = x@rw1
__device__ float g_agg1[(size_t)NN * 32];   // scatter target layer 1
__device__ float g_h1[NN * HID];            // layer-1 output
__device__ float g_agg2[NN * HID];          // scatter target layer 2 (pre-transform)
__device__ float g_W2[HID * 160];           // packed [f][c]: c<80 -> iw2[k][f][c%40], c>=80 -> rw2

// ---------------- helpers ----------------
__device__ __forceinline__ void red_add_v4(float* p, float a, float b, float c, float d) {
    asm volatile("red.global.add.v4.f32 [%0], {%1,%2,%3,%4};"
                 :: "l"(p), "f"(a), "f"(b), "f"(c), "f"(d) : "memory");
}
__device__ __forceinline__ unsigned long long pack_dup(float a) {
    unsigned long long r;
    uint32_t u = __float_as_uint(a);
    asm("mov.b64 %0, {%1, %1};" : "=l"(r) : "r"(u));
    return r;
}
__device__ __forceinline__ void fma2(unsigned long long& acc, unsigned long long a,
                                     unsigned long long b) {
    asm("fma.rn.f32x2 %0, %1, %2, %0;" : "+l"(acc) : "l"(a), "l"(b));
}
__device__ __forceinline__ float2 unpack2(unsigned long long v) {
    uint32_t lo, hi;
    asm("mov.b64 {%0, %1}, %2;" : "=r"(lo), "=r"(hi) : "l"(v));
    return make_float2(__uint_as_float(lo), __uint_as_float(hi));
}

// ---------------- setup kernels ----------------
__global__ void zero_kernel() {
    int i = blockIdx.x * blockDim.x + threadIdx.x;
    if (i < NN) g_deg[i] = 0.f;
    if (i < NN * 32) g_agg1[i] = 0.f;
    if (i < NN * 16) g_agg2[i] = 0.f;
}

__global__ void pack_w1(const float* __restrict__ iw1, const float* __restrict__ rw1) {
    int i = blockIdx.x * blockDim.x + threadIdx.x;
    if (i >= NFEAT * 64) return;
    int f = i >> 6, c = i & 63;
    float v;
    if (c < 32) { int k = c >> 4, j = c & 15; v = iw1[(k * NFEAT + f) * HID + j]; }
    else        { int c2 = c - 32; int k = c2 >> 4, j = c2 & 15; v = rw1[(k * NFEAT + f) * HID + j]; }
    g_W1[i] = v;
}

__global__ void pack_w2(const float* __restrict__ iw2, const float* __restrict__ rw2) {
    int i = blockIdx.x * blockDim.x + threadIdx.x;
    if (i >= HID * 160) return;
    int f = i / 160, c = i % 160;
    float v;
    if (c < 80) { int k = c / 40, o = c % 40; v = iw2[(k * HID + f) * NCLASS + o]; }
    else        { int c2 = c - 80; int k = c2 / 40, o = c2 % 40; v = rw2[(k * HID + f) * NCLASS + o]; }
    g_W2[i] = v;
}

__global__ void deg_kernel(const int* __restrict__ dst, int E) {
    int e = blockIdx.x * blockDim.x + threadIdx.x;
    if (e < E) atomicAdd(&g_deg[__ldg(dst + e)], 1.0f);
}

__global__ void dinv_kernel() {
    int n = blockIdx.x * blockDim.x + threadIdx.x;
    if (n < NN) { float d = g_deg[n]; g_dinv[n] = (d > 0.f) ? rsqrtf(d) : 0.f; }
}

__global__ void ew_kernel(const int* __restrict__ src, const int* __restrict__ dst, int E) {
    int e = blockIdx.x * blockDim.x + threadIdx.x;
    if (e < E) g_ew[e] = g_dinv[__ldg(src + e)] * g_dinv[__ldg(dst + e)];
}

// ---------------- dense: HR[100000,64] = x[100000,512] @ W1[512,64] --------------
// R14 tiling (256 thr, 128x64 block, 8x4 thread) with f32x2 packed inner product.
// Accumulators pair ADJACENT ROWS in one u64 (A pairs read directly from smem);
// only B needs a dup-pack (4 mov.b64 per k-step, ALU pipe).
#define BM 128
#define BK 16
__global__ void gemm1_kernel(const float* __restrict__ x, int nrows) {
    __shared__ float As[BK][BM + 4];         // [k][m], padded (528 B rows, 16B-aligned)
    __shared__ float Bs[BK][64];             // [k][n]
    int tid = threadIdx.x;                   // 256 threads
    int tx = tid & 15, ty = tid >> 4;        // 16 x 16
    int brow = blockIdx.x * BM;

    unsigned long long acc[4][4];            // [row-pair i][col j]: rows ty*8+2i, +1
#pragma unroll
    for (int i = 0; i < 4; i++)
#pragma unroll
        for (int j = 0; j < 4; j++) acc[i][j] = 0ull;

    for (int k0 = 0; k0 < NFEAT; k0 += BK) {
#pragma unroll
        for (int it = 0; it < 2; ++it) {     // A: 128x16 = 512 float4
            int q = tid + it * 256;
            int row = q >> 2, c4 = q & 3;
            int gr = brow + row;
            float4 v = make_float4(0.f, 0.f, 0.f, 0.f);
            if (gr < nrows) v = *(const float4*)&x[(size_t)gr * NFEAT + k0 + c4 * 4];
            As[c4 * 4 + 0][row] = v.x;
            As[c4 * 4 + 1][row] = v.y;
            As[c4 * 4 + 2][row] = v.z;
            As[c4 * 4 + 3][row] = v.w;
        }
        {                                     // B: 16x64 = 256 float4
            int row = tid >> 4, c4 = tid & 15;
            *(float4*)&Bs[row][c4 * 4] = *(const float4*)&g_W1[(k0 + row) * 64 + c4 * 4];
        }
        __syncthreads();
#pragma unroll
        for (int kk = 0; kk < BK; ++kk) {
            // A row-pairs as u64 directly from smem (consecutive m = consecutive floats)
            ulonglong2 A0 = *(const ulonglong2*)&As[kk][ty * 8];
            ulonglong2 A1 = *(const ulonglong2*)&As[kk][ty * 8 + 4];
            unsigned long long ap[4] = {A0.x, A0.y, A1.x, A1.y};
            float4 bf = *(const float4*)&Bs[kk][tx * 4];
            unsigned long long bd[4];
            bd[0] = pack_dup(bf.x); bd[1] = pack_dup(bf.y);
            bd[2] = pack_dup(bf.z); bd[3] = pack_dup(bf.w);
#pragma unroll
            for (int i = 0; i < 4; i++)
#pragma unroll
                for (int j = 0; j < 4; j++) fma2(acc[i][j], ap[i], bd[j]);
        }
        __syncthreads();
    }
#pragma unroll
    for (int i = 0; i < 4; i++) {
        int r0 = brow + ty * 8 + 2 * i;
        float2 c0 = unpack2(acc[i][0]), c1 = unpack2(acc[i][1]);
        float2 c2 = unpack2(acc[i][2]), c3 = unpack2(acc[i][3]);
        if (r0 < nrows)
            *(float4*)&g_HR[(size_t)r0 * 64 + tx * 4] = make_float4(c0.x, c1.x, c2.x, c3.x);
        if (r0 + 1 < nrows)
            *(float4*)&g_HR[(size_t)(r0 + 1) * 64 + tx * 4] = make_float4(c0.y, c1.y, c2.y, c3.y);
    }
}

// ---------------- layer-1 scatter: agg1[dst] += ew * HR[src, 0:32] ----------------
// 4 threads/edge, 8 floats each: 2 LDG.128 + 2 RED.128 per thread.
__global__ void edge1_kernel(const int* __restrict__ src, const int* __restrict__ dst, int E) {
    int idx = blockIdx.x * blockDim.x + threadIdx.x;
    if (idx >= E * 4) return;
    int e = idx >> 2, g = idx & 3;
    int s = __ldg(src + e), d = __ldg(dst + e);
    float w = g_ew[e];
    const float* hp = &g_HR[(size_t)s * 64 + g * 8];
    float4 v0 = *(const float4*)(hp);
    float4 v1 = *(const float4*)(hp + 4);
    float* ap = &g_agg1[(size_t)d * 32 + g * 8];
    red_add_v4(ap,     v0.x * w, v0.y * w, v0.z * w, v0.w * w);
    red_add_v4(ap + 4, v1.x * w, v1.y * w, v1.z * w, v1.w * w);
}

// ---------------- layer-1 epilogue: h1 = mean_k relu(agg1 + x@rw1 + b1) -----------
__global__ void epi1_kernel(const float* __restrict__ b1, int nrows) {
    int i = blockIdx.x * blockDim.x + threadIdx.x;
    if (i >= nrows * HID) return;
    int n = i / HID, j = i - (i / HID) * HID;
    float a0 = g_agg1[(size_t)n * 32 + j]      + g_HR[(size_t)n * 64 + 32 + j] + b1[j];
    float a1 = g_agg1[(size_t)n * 32 + 16 + j] + g_HR[(size_t)n * 64 + 48 + j] + b1[16 + j];
    g_h1[i] = 0.5f * (fmaxf(a0, 0.f) + fmaxf(a1, 0.f));
}

// ---------------- layer-2 scatter (pre-transform): agg2[dst] += ew * h1[src] ------
// 2 threads/edge, 8 floats each.
__global__ void edge2_kernel(const int* __restrict__ src, const int* __restrict__ dst, int E) {
    int idx = blockIdx.x * blockDim.x + threadIdx.x;
    if (idx >= E * 2) return;
    int e = idx >> 1, g = idx & 1;
    int s = __ldg(src + e), d = __ldg(dst + e);
    float w = g_ew[e];
    const float* hp = &g_h1[s * HID + g * 8];
    float4 v0 = *(const float4*)(hp);
    float4 v1 = *(const float4*)(hp + 4);
    float* ap = &g_agg2[d * HID + g * 8];
    red_add_v4(ap,     v0.x * w, v0.y * w, v0.z * w, v0.w * w);
    red_add_v4(ap + 4, v1.x * w, v1.y * w, v1.z * w, v1.w * w);
}

// ---------------- layer-2 transform + epilogue ------------------------------------
__global__ void out_kernel(const float* __restrict__ b2, float* __restrict__ out, int nrows) {
    __shared__ float Ws[HID * 160];
    int tid = threadIdx.x;                   // 320 threads: 8 nodes x 40 outputs
    for (int i = tid; i < HID * 160; i += 320) Ws[i] = g_W2[i];
    __syncthreads();
    int n = blockIdx.x * 8 + tid / 40;
    int o = tid - (tid / 40) * 40;
    if (n >= nrows) return;
    float a[HID], hv[HID];
#pragma unroll
    for (int f = 0; f < HID; ++f) {
        a[f]  = g_agg2[n * HID + f];
        hv[f] = g_h1[n * HID + f];
    }
    float acc0 = b2[o], acc1 = b2[40 + o];
#pragma unroll
    for (int f = 0; f < HID; ++f) {
        const float* wr = &Ws[f * 160];
        acc0 += a[f] * wr[o]      + hv[f] * wr[80 + o];
        acc1 += a[f] * wr[40 + o] + hv[f] * wr[120 + o];
    }
    out[n * 40 + o] = 0.5f * (fmaxf(acc0, 0.f) + fmaxf(acc1, 0.f));
}

// ---------------- launch ----------------
extern "C" void kernel_launch(void* const* d_in, const int* in_sizes, int n_in,
                              void* d_out, int out_size) {
    const float* x   = (const float*)d_in[0];
    const int*   ei  = (const int*)d_in[1];
    const float* iw1 = (const float*)d_in[2];
    const float* rw1 = (const float*)d_in[3];
    const float* b1  = (const float*)d_in[4];
    const float* iw2 = (const float*)d_in[5];
    const float* rw2 = (const float*)d_in[6];
    const float* b2  = (const float*)d_in[7];
    float* out = (float*)d_out;

    int E = in_sizes[1] / 2;
    const int* src = ei;
    const int* dst = ei + E;

    // gemm1 kept in launch slot 4 (the slot ncu profiles).
    zero_kernel<<<(NN * 32 + 255) / 256, 256>>>();
    pack_w1<<<(NFEAT * 64 + 255) / 256, 256>>>(iw1, rw1);
    pack_w2<<<(HID * 160 + 255) / 256, 256>>>(iw2, rw2);
    gemm1_kernel<<<(NN + BM - 1) / BM, 256>>>(x, NN);
    deg_kernel<<<(E + 255) / 256, 256>>>(dst, E);
    dinv_kernel<<<(NN + 255) / 256, 256>>>();
    ew_kernel<<<(E + 255) / 256, 256>>>(src, dst, E);
    edge1_kernel<<<(E * 4 + 255) / 256, 256>>>(src, dst, E);
    epi1_kernel<<<(NN * HID + 255) / 256, 256>>>(b1, NN);
    edge2_kernel<<<(E * 2 + 255) / 256, 256>>>(src, dst, E);
    out_kernel<<<(NN + 7) / 8, 320>>>(b2, out, NN);
}